// round 12
// baseline (speedup 1.0000x reference)
#include <cuda_runtime.h>
#include <cuda_fp16.h>
#include <cuda_bf16.h>
#include <cstdint>
#include <math.h>

#define BB 2
#define SS 2048
#define DM 1024
#define NH 16
#define DH 64
#define MM (BB * SS)   // 4096

// ---------------- scratch (__device__ globals; no allocs) -------------------
__device__ __align__(16) __nv_bfloat16 g_q_hi[MM * DM];
__device__ __align__(16) __nv_bfloat16 g_q_lo[MM * DM];
__device__ __align__(16) __nv_bfloat16 g_k_hi[MM * DM];
__device__ __align__(16) __nv_bfloat16 g_k_lo[MM * DM];
__device__ __align__(16) __nv_bfloat16 g_v_hi[MM * DM];
__device__ __align__(16) __nv_bfloat16 g_v_lo[MM * DM];
__device__ __align__(16) __nv_bfloat16 g_wq_hi[DM * DM];
__device__ __align__(16) __nv_bfloat16 g_wq_lo[DM * DM];
__device__ __align__(16) __nv_bfloat16 g_wk_hi[DM * DM];
__device__ __align__(16) __nv_bfloat16 g_wk_lo[DM * DM];
__device__ __align__(16) __nv_bfloat16 g_wv_hi[DM * DM];
__device__ __align__(16) __nv_bfloat16 g_wv_lo[DM * DM];
__device__ __align__(16) __nv_bfloat16 g_wo_hi[DM * DM];
__device__ __align__(16) __nv_bfloat16 g_wo_lo[DM * DM];
__device__ __align__(16) __half g_qh[MM * DM];   // head-split [bh][s][64] fp16
__device__ __align__(16) __half g_kh[MM * DM];
__device__ __align__(16) __half g_vh[MM * DM];
__device__ __align__(16) __half g_mh[(size_t)BB * SS * SS];  // mask bias fp16
__device__ __align__(16) __nv_bfloat16 g_att_hi[MM * DM];    // head-split
__device__ __align__(16) __nv_bfloat16 g_att_lo[MM * DM];

// ---------------- helpers ---------------------------------------------------
__device__ __forceinline__ uint32_t smem_u32(const void* p) {
    uint32_t a;
    asm("{ .reg .u64 t; cvta.to.shared.u64 t, %1; cvt.u32.u64 %0, t; }"
        : "=r"(a) : "l"(p));
    return a;
}
__device__ __forceinline__ float ex2(float x) {
    float y;
    asm("ex2.approx.ftz.f32 %0, %1;" : "=f"(y) : "f"(x));
    return y;
}
__device__ __forceinline__ uint32_t pack2h(float lo, float hi) {
    uint32_t r;
    asm("cvt.rn.f16x2.f32 %0, %1, %2;" : "=r"(r) : "f"(hi), "f"(lo));
    return r;
}
__device__ __forceinline__ void mma_bf16(float d[4], uint32_t a0, uint32_t a1,
                                         uint32_t a2, uint32_t a3,
                                         uint32_t b0, uint32_t b1) {
    asm("mma.sync.aligned.m16n8k16.row.col.f32.bf16.bf16.f32 "
        "{%0,%1,%2,%3},{%4,%5,%6,%7},{%8,%9},{%0,%1,%2,%3};"
        : "+f"(d[0]), "+f"(d[1]), "+f"(d[2]), "+f"(d[3])
        : "r"(a0), "r"(a1), "r"(a2), "r"(a3), "r"(b0), "r"(b1));
}
__device__ __forceinline__ void mma_f16(float d[4], uint32_t a0, uint32_t a1,
                                        uint32_t a2, uint32_t a3,
                                        uint32_t b0, uint32_t b1) {
    asm("mma.sync.aligned.m16n8k16.row.col.f32.f16.f16.f32 "
        "{%0,%1,%2,%3},{%4,%5,%6,%7},{%8,%9},{%0,%1,%2,%3};"
        : "+f"(d[0]), "+f"(d[1]), "+f"(d[2]), "+f"(d[3])
        : "r"(a0), "r"(a1), "r"(a2), "r"(a3), "r"(b0), "r"(b1));
}
__device__ __forceinline__ void ldmx4(uint32_t r[4], uint32_t addr) {
    asm volatile("ldmatrix.sync.aligned.m8n8.x4.shared.b16 {%0,%1,%2,%3}, [%4];"
                 : "=r"(r[0]), "=r"(r[1]), "=r"(r[2]), "=r"(r[3]) : "r"(addr));
}
__device__ __forceinline__ void ldmx4t(uint32_t r[4], uint32_t addr) {
    asm volatile("ldmatrix.sync.aligned.m8n8.x4.trans.shared.b16 {%0,%1,%2,%3}, [%4];"
                 : "=r"(r[0]), "=r"(r[1]), "=r"(r[2]), "=r"(r[3]) : "r"(addr));
}
__device__ __forceinline__ void cpa16(uint32_t dst, const void* src) {
    asm volatile("cp.async.ca.shared.global [%0], [%1], 16;" :: "r"(dst), "l"(src));
}
#define CP_COMMIT() asm volatile("cp.async.commit_group;")
#define CP_WAIT(n)  asm volatile("cp.async.wait_group %0;" :: "n"(n))

// ---------------- fp32 -> (hi,lo) bf16 split, z-batched ---------------------
__device__ __forceinline__ void split_body(const float4* __restrict__ x,
                                           __nv_bfloat162* __restrict__ hi,
                                           __nv_bfloat162* __restrict__ lo)
{
    int i = blockIdx.x * blockDim.x + threadIdx.x;
    float4 v = x[i];
    __nv_bfloat16 h0 = __float2bfloat16(v.x), h1 = __float2bfloat16(v.y);
    __nv_bfloat16 h2 = __float2bfloat16(v.z), h3 = __float2bfloat16(v.w);
    __nv_bfloat16 l0 = __float2bfloat16(v.x - __bfloat162float(h0));
    __nv_bfloat16 l1 = __float2bfloat16(v.y - __bfloat162float(h1));
    __nv_bfloat16 l2 = __float2bfloat16(v.z - __bfloat162float(h2));
    __nv_bfloat16 l3 = __float2bfloat16(v.w - __bfloat162float(h3));
    hi[i * 2]     = __nv_bfloat162(h0, h1);
    hi[i * 2 + 1] = __nv_bfloat162(h2, h3);
    lo[i * 2]     = __nv_bfloat162(l0, l1);
    lo[i * 2 + 1] = __nv_bfloat162(l2, l3);
}

__global__ __launch_bounds__(256)
void split_qkv(const float4* __restrict__ s0, const float4* __restrict__ s1,
               const float4* __restrict__ s2,
               __nv_bfloat162* __restrict__ h0, __nv_bfloat162* __restrict__ h1,
               __nv_bfloat162* __restrict__ h2,
               __nv_bfloat162* __restrict__ l0, __nv_bfloat162* __restrict__ l1,
               __nv_bfloat162* __restrict__ l2)
{
    int z = blockIdx.z;
    const float4* s = (z == 0) ? s0 : (z == 1) ? s1 : s2;
    __nv_bfloat162* h = (z == 0) ? h0 : (z == 1) ? h1 : h2;
    __nv_bfloat162* l = (z == 0) ? l0 : (z == 1) ? l1 : l2;
    split_body(s, h, l);
}

__global__ __launch_bounds__(256)
void split_w(const float4* __restrict__ s0, const float4* __restrict__ s1,
             const float4* __restrict__ s2, const float4* __restrict__ s3,
             __nv_bfloat162* __restrict__ h0, __nv_bfloat162* __restrict__ h1,
             __nv_bfloat162* __restrict__ h2, __nv_bfloat162* __restrict__ h3,
             __nv_bfloat162* __restrict__ l0, __nv_bfloat162* __restrict__ l1,
             __nv_bfloat162* __restrict__ l2, __nv_bfloat162* __restrict__ l3)
{
    int z = blockIdx.z;
    const float4* s = (z == 0) ? s0 : (z == 1) ? s1 : (z == 2) ? s2 : s3;
    __nv_bfloat162* h = (z == 0) ? h0 : (z == 1) ? h1 : (z == 2) ? h2 : h3;
    __nv_bfloat162* l = (z == 0) ? l0 : (z == 1) ? l1 : (z == 2) ? l2 : l3;
    split_body(s, h, l);
}

// ---------------- mask -> fp16 bias ----------------------------------------
__global__ __launch_bounds__(256)
void pre_mask(const float4* __restrict__ m, __half2* __restrict__ o)
{
    int i = blockIdx.x * blockDim.x + threadIdx.x;
    float4 v = m[i];
    o[2 * i]     = __floats2half2_rn(v.x * -60000.f, v.y * -60000.f);
    o[2 * i + 1] = __floats2half2_rn(v.z * -60000.f, v.w * -60000.f);
}

// ---------------- projection GEMM body (round-5/11 proven) ------------------
// Block 128M x 128N, K-chunk 32, 8 warps (warp tile 32x64), bf16x3,
// 2-stage cp.async. MODE0: fp16 head-split out. MODE1: fp32 [M,N] out.
#define PSTG 16384
#define PROJ_SMEM (2 * PSTG * 2)

template <int MODE>
__device__ __forceinline__
void proj_body(const uint4* __restrict__ Ahi, const uint4* __restrict__ Alo,
               const uint4* __restrict__ Bhi, const uint4* __restrict__ Blo,
               const float* __restrict__ bias, void* __restrict__ outp,
               ushort* ps)
{
    const uint32_t sbase = smem_u32(ps);

    const int tid = threadIdx.x;
    const int lane = tid & 31, wid = tid >> 5;
    const int g = lane >> 2, t = lane & 3;
    const int m0 = blockIdx.y * 128;
    const int n0 = blockIdx.x * 128;
    const int wm = (wid & 3) * 32;
    const int wn = (wid >> 2) * 64;

    float d[2][8][4];
#pragma unroll
    for (int mt = 0; mt < 2; mt++)
#pragma unroll
        for (int nt = 0; nt < 8; nt++)
#pragma unroll
            for (int e = 0; e < 4; e++) d[mt][nt][e] = 0.f;

    auto load_stage = [&](int stage, int it) {
        const int k0 = it * 32;
        const uint32_t sb = sbase + stage * (PSTG * 2);
#pragma unroll
        for (int s = 0; s < 2; s++) {
            int idx = tid + s * 256;
            int r = idx >> 2, gg = idx & 3;
            uint32_t doff = (uint32_t)(r * 32 + ((gg ^ ((r >> 1) & 3)) * 8)) * 2;
            size_t ia;
            if (MODE == 0) {
                ia = (size_t)(m0 + r) * 128 + (k0 >> 3) + gg;
            } else {
                int m = m0 + r;
                int b = m >> 11, ss2 = m & (SS - 1);
                int h = k0 >> 6;
                ia = ((size_t)((b * NH + h) * SS + ss2)) * 8 + ((k0 & 63) >> 3) + gg;
            }
            size_t ib = (size_t)(n0 + r) * 128 + (k0 >> 3) + gg;
            cpa16(sb + doff,         &Ahi[ia]);
            cpa16(sb + 8192 + doff,  &Alo[ia]);
            cpa16(sb + 16384 + doff, &Bhi[ib]);
            cpa16(sb + 24576 + doff, &Blo[ib]);
        }
    };

    load_stage(0, 0);
    CP_COMMIT();

    for (int it = 0; it < 32; ++it) {
        const int cur = it & 1;
        if (it < 31) { load_stage(cur ^ 1, it + 1); CP_COMMIT(); }
        if (it < 31) { CP_WAIT(1); } else { CP_WAIT(0); }
        __syncthreads();

        const uint32_t sb = sbase + cur * (PSTG * 2);
#pragma unroll
        for (int ks = 0; ks < 2; ks++) {
            uint32_t ah[2][4], al[2][4];
#pragma unroll
            for (int mt = 0; mt < 2; mt++) {
                int row = wm + 16 * mt + (lane & 15);
                int gg = (2 * ks + (lane >> 4)) ^ ((row >> 1) & 3);
                uint32_t ao = (uint32_t)(row * 32 + gg * 8) * 2;
                ldmx4(ah[mt], sb + ao);
                ldmx4(al[mt], sb + 8192 + ao);
            }
#pragma unroll
            for (int p = 0; p < 4; p++) {
                int row = wn + 16 * p + ((lane >> 4) << 3) + (lane & 7);
                int gg = (2 * ks + ((lane >> 3) & 1)) ^ ((row >> 1) & 3);
                uint32_t bo = (uint32_t)(row * 32 + gg * 8) * 2;
                uint32_t bh4[4], bl4[4];
                ldmx4(bh4, sb + 16384 + bo);
                ldmx4(bl4, sb + 24576 + bo);
#pragma unroll
                for (int mt = 0; mt < 2; mt++) {
                    mma_bf16(d[mt][2 * p],     ah[mt][0], ah[mt][1], ah[mt][2], ah[mt][3], bh4[0], bh4[1]);
                    mma_bf16(d[mt][2 * p + 1], ah[mt][0], ah[mt][1], ah[mt][2], ah[mt][3], bh4[2], bh4[3]);
                    mma_bf16(d[mt][2 * p],     ah[mt][0], ah[mt][1], ah[mt][2], ah[mt][3], bl4[0], bl4[1]);
                    mma_bf16(d[mt][2 * p + 1], ah[mt][0], ah[mt][1], ah[mt][2], ah[mt][3], bl4[2], bl4[3]);
                    mma_bf16(d[mt][2 * p],     al[mt][0], al[mt][1], al[mt][2], al[mt][3], bh4[0], bh4[1]);
                    mma_bf16(d[mt][2 * p + 1], al[mt][0], al[mt][1], al[mt][2], al[mt][3], bh4[2], bh4[3]);
                }
            }
        }
        __syncthreads();
    }

    // epilogue
#pragma unroll
    for (int mt = 0; mt < 2; mt++) {
#pragma unroll
        for (int nt = 0; nt < 8; nt++) {
            int m = m0 + wm + 16 * mt + g;
            int n = n0 + wn + 8 * nt + 2 * t;
            float2 bv = *(const float2*)&bias[n];
            float v0 = d[mt][nt][0] + bv.x, v1 = d[mt][nt][1] + bv.y;
            float v2 = d[mt][nt][2] + bv.x, v3 = d[mt][nt][3] + bv.y;
            if (MODE == 0) {
                int h = n >> 6, dh = n & 63;
                int b = m >> 11, ss2 = m & (SS - 1);
                __half* o = (__half*)outp;
                size_t o0 = ((size_t)((b * NH + h) * SS + ss2)) * DH + dh;
                size_t o1 = ((size_t)((b * NH + h) * SS + ss2 + 8)) * DH + dh;
                *(__half2*)&o[o0] = __floats2half2_rn(v0, v1);
                *(__half2*)&o[o1] = __floats2half2_rn(v2, v3);
            } else {
                float* o = (float*)outp;
                *(float2*)&o[(size_t)m * DM + n] = make_float2(v0, v1);
                *(float2*)&o[(size_t)(m + 8) * DM + n] = make_float2(v2, v3);
            }
        }
    }
}

// Merged Q/K/V projection: blockIdx.z selects the GEMM.
__global__ __launch_bounds__(256)
void proj_qkv(const uint4* Ah0, const uint4* Al0, const uint4* Bh0, const uint4* Bl0,
              const float* b0, void* o0,
              const uint4* Ah1, const uint4* Al1, const uint4* Bh1, const uint4* Bl1,
              const float* b1, void* o1,
              const uint4* Ah2, const uint4* Al2, const uint4* Bh2, const uint4* Bl2,
              const float* b2, void* o2)
{
    extern __shared__ __align__(16) ushort ps[];
    int z = blockIdx.z;
    const uint4* Ahi = (z == 0) ? Ah0 : (z == 1) ? Ah1 : Ah2;
    const uint4* Alo = (z == 0) ? Al0 : (z == 1) ? Al1 : Al2;
    const uint4* Bhi = (z == 0) ? Bh0 : (z == 1) ? Bh1 : Bh2;
    const uint4* Blo = (z == 0) ? Bl0 : (z == 1) ? Bl1 : Bl2;
    const float* bias = (z == 0) ? b0 : (z == 1) ? b1 : b2;
    void* outp = (z == 0) ? o0 : (z == 1) ? o1 : o2;
    proj_body<0>(Ahi, Alo, Bhi, Blo, bias, outp, ps);
}

// Output projection (A gathered from head-split attention output).
__global__ __launch_bounds__(256)
void proj_o(const uint4* __restrict__ Ahi, const uint4* __restrict__ Alo,
            const uint4* __restrict__ Bhi, const uint4* __restrict__ Blo,
            const float* __restrict__ bias, void* __restrict__ outp)
{
    extern __shared__ __align__(16) ushort ps[];
    proj_body<1>(Ahi, Alo, Bhi, Blo, bias, outp, ps);
}

// ---------------- flash attention (round-11 proven: q-tile 128) -------------
__global__ __launch_bounds__(128)
void flash_attn()
{
    __shared__ __align__(16) ushort Qs[128 * 64];
    __shared__ __align__(16) ushort Ks[2][64 * 64];
    __shared__ __align__(16) ushort Vs[2][64 * 64];

    const int tid = threadIdx.x;
    const int lane = tid & 31, w = tid >> 5;
    const int g = lane >> 2, t = lane & 3;
    const int bh = blockIdx.y, b = bh >> 4;
    const int q0 = blockIdx.x * 128;

    const float C1 = 0.125f * 1.4426950408889634f;
    const float SC = 0.015625f;

    const uint32_t Qb  = smem_u32(Qs);
    const uint32_t Kb0 = smem_u32(Ks);
    const uint32_t Vb0 = smem_u32(Vs);

    const uint4* qsrc = (const uint4*)g_qh;
#pragma unroll
    for (int s = 0; s < 8; s++) {
        int f = tid + s * 128;
        int r = f >> 3, c = f & 7;
        uint4 v = qsrc[((size_t)bh * SS + q0 + r) * 8 + c];
        *(uint4*)&Qs[r * 64 + ((c ^ (r & 7)) << 3)] = v;
    }

    const char* ksrc = (const char*)(g_kh + (size_t)bh * SS * DH);
    const char* vsrc = (const char*)(g_vh + (size_t)bh * SS * DH);

    auto load_kv = [&](int stage, int kt) {
#pragma unroll
        for (int s = 0; s < 4; s++) {
            int f = tid + s * 128;
            int r = f >> 3, c = f & 7;
            uint32_t doff = (uint32_t)(r * 64 + ((c ^ (r & 7)) << 3)) * 2;
            size_t go = ((size_t)(kt + r) * 8 + c) * 16;
            cpa16(Kb0 + stage * 8192 + doff, ksrc + go);
            cpa16(Vb0 + stage * 8192 + doff, vsrc + go);
        }
    };

    float O[2][8][4];
#pragma unroll
    for (int mt = 0; mt < 2; mt++)
#pragma unroll
        for (int j = 0; j < 8; j++)
#pragma unroll
            for (int e = 0; e < 4; e++) O[mt][j][e] = 0.f;
    float lsum[2][2] = {{0.f, 0.f}, {0.f, 0.f}};

    load_kv(0, 0);
    CP_COMMIT();

    for (int itn = 0; itn < 32; ++itn) {
        const int cur = itn & 1;
        const int kt = itn * 64;
        if (itn < 31) { load_kv(cur ^ 1, kt + 64); CP_COMMIT(); }
        if (itn < 31) { CP_WAIT(1); } else { CP_WAIT(0); }
        __syncthreads();

        const uint32_t Kb = Kb0 + cur * 8192;
        const uint32_t Vb = Vb0 + cur * 8192;

        uint32_t pA[2][8], pB[2][8];

#pragma unroll
        for (int mt = 0; mt < 2; mt++) {
            float sd[8][4];
#pragma unroll
            for (int j = 0; j < 8; j++)
#pragma unroll
                for (int e = 0; e < 4; e++) sd[j][e] = 0.f;

#pragma unroll
            for (int ks = 0; ks < 4; ks++) {
                uint32_t a4[4];
                {
                    int row = 32 * w + 16 * mt + (lane & 15);
                    int gg = (2 * ks + (lane >> 4)) ^ (row & 7);
                    ldmx4(a4, Qb + (uint32_t)(row * 64 + gg * 8) * 2);
                }
#pragma unroll
                for (int p = 0; p < 4; p++) {
                    int row = 16 * p + ((lane >> 4) << 3) + (lane & 7);
                    int gg = (2 * ks + ((lane >> 3) & 1)) ^ (row & 7);
                    uint32_t b4[4];
                    ldmx4(b4, Kb + (uint32_t)(row * 64 + gg * 8) * 2);
                    mma_f16(sd[2 * p],     a4[0], a4[1], a4[2], a4[3], b4[0], b4[1]);
                    mma_f16(sd[2 * p + 1], a4[0], a4[1], a4[2], a4[3], b4[2], b4[3]);
                }
            }

            const __half2* mrow0 =
                (const __half2*)&g_mh[((size_t)b * SS + q0 + 32 * w + 16 * mt + g) * SS + kt];
            const __half2* mrow1 =
                (const __half2*)&g_mh[((size_t)b * SS + q0 + 32 * w + 16 * mt + g + 8) * SS + kt];
#pragma unroll
            for (int j = 0; j < 8; j++) {
                float2 mb0 = __half22float2(mrow0[4 * j + t]);
                float2 mb1 = __half22float2(mrow1[4 * j + t]);
                float p0 = ex2(fmaf(sd[j][0], C1, mb0.x));
                float p1 = ex2(fmaf(sd[j][1], C1, mb0.y));
                float p2 = ex2(fmaf(sd[j][2], C1, mb1.x));
                float p3 = ex2(fmaf(sd[j][3], C1, mb1.y));
                lsum[mt][0] += p0 + p1;
                lsum[mt][1] += p2 + p3;
                pA[mt][j] = pack2h(p0 * SC, p1 * SC);
                pB[mt][j] = pack2h(p2 * SC, p3 * SC);
            }
        }

#pragma unroll
        for (int c2 = 0; c2 < 4; c2++) {
#pragma unroll
            for (int jp = 0; jp < 4; jp++) {
                int row = 16 * c2 + (((lane >> 3) & 1) << 3) + (lane & 7);
                int gg = (2 * jp + (lane >> 4)) ^ (row & 7);
                uint32_t b4[4];
                ldmx4t(b4, Vb + (uint32_t)(row * 64 + gg * 8) * 2);
#pragma unroll
                for (int mt = 0; mt < 2; mt++) {
                    mma_f16(O[mt][2 * jp],     pA[mt][2 * c2], pB[mt][2 * c2],
                            pA[mt][2 * c2 + 1], pB[mt][2 * c2 + 1], b4[0], b4[1]);
                    mma_f16(O[mt][2 * jp + 1], pA[mt][2 * c2], pB[mt][2 * c2],
                            pA[mt][2 * c2 + 1], pB[mt][2 * c2 + 1], b4[2], b4[3]);
                }
            }
        }
        __syncthreads();
    }

#pragma unroll
    for (int mt = 0; mt < 2; mt++) {
        float l0 = lsum[mt][0], l1 = lsum[mt][1];
        l0 += __shfl_xor_sync(0xffffffffu, l0, 1);
        l0 += __shfl_xor_sync(0xffffffffu, l0, 2);
        l1 += __shfl_xor_sync(0xffffffffu, l1, 1);
        l1 += __shfl_xor_sync(0xffffffffu, l1, 2);
        const float inv0 = 64.f / l0;
        const float inv1 = 64.f / l1;

        size_t off0 = ((size_t)bh * SS + q0 + 32 * w + 16 * mt + g) * DH;
        size_t off1 = ((size_t)bh * SS + q0 + 32 * w + 16 * mt + g + 8) * DH;
#pragma unroll
        for (int j = 0; j < 8; j++) {
            int dh = 8 * j + 2 * t;
            float v0 = O[mt][j][0] * inv0, v1 = O[mt][j][1] * inv0;
            float v2 = O[mt][j][2] * inv1, v3 = O[mt][j][3] * inv1;
            __nv_bfloat16 h0 = __float2bfloat16(v0), h1 = __float2bfloat16(v1);
            __nv_bfloat16 h2 = __float2bfloat16(v2), h3 = __float2bfloat16(v3);
            __nv_bfloat16 e0 = __float2bfloat16(v0 - __bfloat162float(h0));
            __nv_bfloat16 e1 = __float2bfloat16(v1 - __bfloat162float(h1));
            __nv_bfloat16 e2 = __float2bfloat16(v2 - __bfloat162float(h2));
            __nv_bfloat16 e3 = __float2bfloat16(v3 - __bfloat162float(h3));
            *(__nv_bfloat162*)&g_att_hi[off0 + dh] = __nv_bfloat162(h0, h1);
            *(__nv_bfloat162*)&g_att_lo[off0 + dh] = __nv_bfloat162(e0, e1);
            *(__nv_bfloat162*)&g_att_hi[off1 + dh] = __nv_bfloat162(h2, h3);
            *(__nv_bfloat162*)&g_att_lo[off1 + dh] = __nv_bfloat162(e2, e3);
        }
    }
}

// ---------------------------------------------------------------------------
extern "C" void kernel_launch(void* const* d_in, const int* in_sizes, int n_in,
                              void* d_out, int out_size)
{
    const float* q    = (const float*)d_in[0];
    const float* k    = (const float*)d_in[1];
    const float* v    = (const float*)d_in[2];
    const float* mask = (const float*)d_in[3];
    const float* wq   = (const float*)d_in[4];
    const float* bq   = (const float*)d_in[5];
    const float* wk   = (const float*)d_in[6];
    const float* bk   = (const float*)d_in[7];
    const float* wv   = (const float*)d_in[8];
    const float* bv   = (const float*)d_in[9];
    const float* wo   = (const float*)d_in[10];
    const float* bo   = (const float*)d_in[11];
    float* out = (float*)d_out;

    void *qh_, *ql_, *kh_, *kl_, *vh_, *vl_;
    void *wqh_, *wql_, *wkh_, *wkl_, *wvh_, *wvl_, *woh_, *wol_;
    void *pqh_, *pkh_, *pvh_, *ath_, *atl_, *mh_;
    cudaGetSymbolAddress(&qh_, g_q_hi);   cudaGetSymbolAddress(&ql_, g_q_lo);
    cudaGetSymbolAddress(&kh_, g_k_hi);   cudaGetSymbolAddress(&kl_, g_k_lo);
    cudaGetSymbolAddress(&vh_, g_v_hi);   cudaGetSymbolAddress(&vl_, g_v_lo);
    cudaGetSymbolAddress(&wqh_, g_wq_hi); cudaGetSymbolAddress(&wql_, g_wq_lo);
    cudaGetSymbolAddress(&wkh_, g_wk_hi); cudaGetSymbolAddress(&wkl_, g_wk_lo);
    cudaGetSymbolAddress(&wvh_, g_wv_hi); cudaGetSymbolAddress(&wvl_, g_wv_lo);
    cudaGetSymbolAddress(&woh_, g_wo_hi); cudaGetSymbolAddress(&wol_, g_wo_lo);
    cudaGetSymbolAddress(&pqh_, g_qh);    cudaGetSymbolAddress(&pkh_, g_kh);
    cudaGetSymbolAddress(&pvh_, g_vh);
    cudaGetSymbolAddress(&ath_, g_att_hi); cudaGetSymbolAddress(&atl_, g_att_lo);
    cudaGetSymbolAddress(&mh_, g_mh);

    cudaFuncSetAttribute(proj_qkv, cudaFuncAttributeMaxDynamicSharedMemorySize, PROJ_SMEM);
    cudaFuncSetAttribute(proj_o,   cudaFuncAttributeMaxDynamicSharedMemorySize, PROJ_SMEM);

    // Launch 1: q,k,v splits (grid.z = 3)
    {
        dim3 sgrid(MM * DM / 4 / 256, 1, 3);
        split_qkv<<<sgrid, 256>>>(
            (const float4*)q, (const float4*)k, (const float4*)v,
            (__nv_bfloat162*)qh_, (__nv_bfloat162*)kh_, (__nv_bfloat162*)vh_,
            (__nv_bfloat162*)ql_, (__nv_bfloat162*)kl_, (__nv_bfloat162*)vl_);
    }
    // Launch 2: weight splits (grid.z = 4)
    {
        dim3 sgrid(DM * DM / 4 / 256, 1, 4);
        split_w<<<sgrid, 256>>>(
            (const float4*)wq, (const float4*)wk, (const float4*)wv, (const float4*)wo,
            (__nv_bfloat162*)wqh_, (__nv_bfloat162*)wkh_, (__nv_bfloat162*)wvh_,
            (__nv_bfloat162*)woh_,
            (__nv_bfloat162*)wql_, (__nv_bfloat162*)wkl_, (__nv_bfloat162*)wvl_,
            (__nv_bfloat162*)wol_);
    }
    // Launch 3: mask -> fp16 bias
    pre_mask<<<BB * SS * SS / 4 / 256, 256>>>((const float4*)mask, (__half2*)mh_);

    // Launch 4: merged Q/K/V projections (grid.z = 3)
    {
        dim3 pgrid(DM / 128, MM / 128, 3);   // (8, 32, 3)
        proj_qkv<<<pgrid, 256, PROJ_SMEM>>>(
            (const uint4*)qh_, (const uint4*)ql_, (const uint4*)wqh_, (const uint4*)wql_, bq, pqh_,
            (const uint4*)kh_, (const uint4*)kl_, (const uint4*)wkh_, (const uint4*)wkl_, bk, pkh_,
            (const uint4*)vh_, (const uint4*)vl_, (const uint4*)wvh_, (const uint4*)wvl_, bv, pvh_);
    }

    // Launch 5: attention
    dim3 agrid(SS / 128, BB * NH);    // (16, 32)
    flash_attn<<<agrid, 128>>>();

    // Launch 6 (ncu target): output projection
    dim3 ogrid(DM / 128, MM / 128);   // (8, 32)
    proj_o<<<ogrid, 256, PROJ_SMEM>>>((const uint4*)ath_, (const uint4*)atl_,
                                      (const uint4*)woh_, (const uint4*)wol_, bo, out);
}

// round 14
// speedup vs baseline: 1.0730x; 1.0730x over previous
#include <cuda_runtime.h>
#include <cuda_fp16.h>
#include <cuda_bf16.h>
#include <cstdint>
#include <math.h>

#define BB 2
#define SS 2048
#define DM 1024
#define NH 16
#define DH 64
#define MM (BB * SS)   // 4096

// ---------------- scratch (__device__ globals; no allocs) -------------------
__device__ __align__(16) __nv_bfloat16 g_q_hi[MM * DM];
__device__ __align__(16) __nv_bfloat16 g_q_lo[MM * DM];
__device__ __align__(16) __nv_bfloat16 g_k_hi[MM * DM];
__device__ __align__(16) __nv_bfloat16 g_k_lo[MM * DM];
__device__ __align__(16) __nv_bfloat16 g_v_hi[MM * DM];
__device__ __align__(16) __nv_bfloat16 g_v_lo[MM * DM];
__device__ __align__(16) __nv_bfloat16 g_wq_hi[DM * DM];
__device__ __align__(16) __nv_bfloat16 g_wq_lo[DM * DM];
__device__ __align__(16) __nv_bfloat16 g_wk_hi[DM * DM];
__device__ __align__(16) __nv_bfloat16 g_wk_lo[DM * DM];
__device__ __align__(16) __nv_bfloat16 g_wv_hi[DM * DM];
__device__ __align__(16) __nv_bfloat16 g_wv_lo[DM * DM];
__device__ __align__(16) __nv_bfloat16 g_wo_hi[DM * DM];
__device__ __align__(16) __nv_bfloat16 g_wo_lo[DM * DM];
__device__ __align__(16) __half g_qh[MM * DM];   // head-split [bh][s][64] fp16
__device__ __align__(16) __half g_kh[MM * DM];
__device__ __align__(16) __half g_vh[MM * DM];
__device__ __align__(16) __half g_mh[(size_t)BB * SS * SS];  // mask bias fp16
__device__ __align__(16) __nv_bfloat16 g_att_hi[MM * DM];    // head-split
__device__ __align__(16) __nv_bfloat16 g_att_lo[MM * DM];

// ---------------- helpers ---------------------------------------------------
__device__ __forceinline__ uint32_t smem_u32(const void* p) {
    uint32_t a;
    asm("{ .reg .u64 t; cvta.to.shared.u64 t, %1; cvt.u32.u64 %0, t; }"
        : "=r"(a) : "l"(p));
    return a;
}
__device__ __forceinline__ float ex2(float x) {
    float y;
    asm("ex2.approx.ftz.f32 %0, %1;" : "=f"(y) : "f"(x));
    return y;
}
__device__ __forceinline__ uint32_t pack2h(float lo, float hi) {
    uint32_t r;
    asm("cvt.rn.f16x2.f32 %0, %1, %2;" : "=r"(r) : "f"(hi), "f"(lo));
    return r;
}
__device__ __forceinline__ void mma_bf16(float d[4], uint32_t a0, uint32_t a1,
                                         uint32_t a2, uint32_t a3,
                                         uint32_t b0, uint32_t b1) {
    asm("mma.sync.aligned.m16n8k16.row.col.f32.bf16.bf16.f32 "
        "{%0,%1,%2,%3},{%4,%5,%6,%7},{%8,%9},{%0,%1,%2,%3};"
        : "+f"(d[0]), "+f"(d[1]), "+f"(d[2]), "+f"(d[3])
        : "r"(a0), "r"(a1), "r"(a2), "r"(a3), "r"(b0), "r"(b1));
}
__device__ __forceinline__ void mma_f16(float d[4], uint32_t a0, uint32_t a1,
                                        uint32_t a2, uint32_t a3,
                                        uint32_t b0, uint32_t b1) {
    asm("mma.sync.aligned.m16n8k16.row.col.f32.f16.f16.f32 "
        "{%0,%1,%2,%3},{%4,%5,%6,%7},{%8,%9},{%0,%1,%2,%3};"
        : "+f"(d[0]), "+f"(d[1]), "+f"(d[2]), "+f"(d[3])
        : "r"(a0), "r"(a1), "r"(a2), "r"(a3), "r"(b0), "r"(b1));
}
__device__ __forceinline__ void ldmx4(uint32_t r[4], uint32_t addr) {
    asm volatile("ldmatrix.sync.aligned.m8n8.x4.shared.b16 {%0,%1,%2,%3}, [%4];"
                 : "=r"(r[0]), "=r"(r[1]), "=r"(r[2]), "=r"(r[3]) : "r"(addr));
}
__device__ __forceinline__ void ldmx4t(uint32_t r[4], uint32_t addr) {
    asm volatile("ldmatrix.sync.aligned.m8n8.x4.trans.shared.b16 {%0,%1,%2,%3}, [%4];"
                 : "=r"(r[0]), "=r"(r[1]), "=r"(r[2]), "=r"(r[3]) : "r"(addr));
}
__device__ __forceinline__ void cpa16(uint32_t dst, const void* src) {
    asm volatile("cp.async.ca.shared.global [%0], [%1], 16;" :: "r"(dst), "l"(src));
}
#define CP_COMMIT() asm volatile("cp.async.commit_group;")
#define CP_WAIT(n)  asm volatile("cp.async.wait_group %0;" :: "n"(n))

// ---------------- fp32 -> (hi,lo) bf16 split, z-batched ---------------------
__device__ __forceinline__ void split_body(const float4* __restrict__ x,
                                           __nv_bfloat162* __restrict__ hi,
                                           __nv_bfloat162* __restrict__ lo)
{
    int i = blockIdx.x * blockDim.x + threadIdx.x;
    float4 v = x[i];
    __nv_bfloat16 h0 = __float2bfloat16(v.x), h1 = __float2bfloat16(v.y);
    __nv_bfloat16 h2 = __float2bfloat16(v.z), h3 = __float2bfloat16(v.w);
    __nv_bfloat16 l0 = __float2bfloat16(v.x - __bfloat162float(h0));
    __nv_bfloat16 l1 = __float2bfloat16(v.y - __bfloat162float(h1));
    __nv_bfloat16 l2 = __float2bfloat16(v.z - __bfloat162float(h2));
    __nv_bfloat16 l3 = __float2bfloat16(v.w - __bfloat162float(h3));
    hi[i * 2]     = __nv_bfloat162(h0, h1);
    hi[i * 2 + 1] = __nv_bfloat162(h2, h3);
    lo[i * 2]     = __nv_bfloat162(l0, l1);
    lo[i * 2 + 1] = __nv_bfloat162(l2, l3);
}

__global__ __launch_bounds__(256)
void split_qkv(const float4* __restrict__ s0, const float4* __restrict__ s1,
               const float4* __restrict__ s2,
               __nv_bfloat162* __restrict__ h0, __nv_bfloat162* __restrict__ h1,
               __nv_bfloat162* __restrict__ h2,
               __nv_bfloat162* __restrict__ l0, __nv_bfloat162* __restrict__ l1,
               __nv_bfloat162* __restrict__ l2)
{
    int z = blockIdx.z;
    const float4* s = (z == 0) ? s0 : (z == 1) ? s1 : s2;
    __nv_bfloat162* h = (z == 0) ? h0 : (z == 1) ? h1 : h2;
    __nv_bfloat162* l = (z == 0) ? l0 : (z == 1) ? l1 : l2;
    split_body(s, h, l);
}

__global__ __launch_bounds__(256)
void split_w(const float4* __restrict__ s0, const float4* __restrict__ s1,
             const float4* __restrict__ s2, const float4* __restrict__ s3,
             __nv_bfloat162* __restrict__ h0, __nv_bfloat162* __restrict__ h1,
             __nv_bfloat162* __restrict__ h2, __nv_bfloat162* __restrict__ h3,
             __nv_bfloat162* __restrict__ l0, __nv_bfloat162* __restrict__ l1,
             __nv_bfloat162* __restrict__ l2, __nv_bfloat162* __restrict__ l3)
{
    int z = blockIdx.z;
    const float4* s = (z == 0) ? s0 : (z == 1) ? s1 : (z == 2) ? s2 : s3;
    __nv_bfloat162* h = (z == 0) ? h0 : (z == 1) ? h1 : (z == 2) ? h2 : h3;
    __nv_bfloat162* l = (z == 0) ? l0 : (z == 1) ? l1 : (z == 2) ? l2 : l3;
    split_body(s, h, l);
}

// ---------------- mask -> fp16 bias ----------------------------------------
__global__ __launch_bounds__(256)
void pre_mask(const float4* __restrict__ m, __half2* __restrict__ o)
{
    int i = blockIdx.x * blockDim.x + threadIdx.x;
    float4 v = m[i];
    o[2 * i]     = __floats2half2_rn(v.x * -60000.f, v.y * -60000.f);
    o[2 * i + 1] = __floats2half2_rn(v.z * -60000.f, v.w * -60000.f);
}

// ---------------- projection GEMM body ---------------------------------------
// Block 128M x 128N, K-chunk 32, 8 warps (warp tile 32x64), bf16x3,
// 2-stage cp.async. Register-dieted: A-hi and A-lo processed in separate
// scopes with a single 4-reg B buffer -> peak live ~105 regs, so the
// __launch_bounds__(256,2) cap (128) binds WITHOUT spilling (spills would
// grow local memory at capture = allocation-guard violation).
#define PSTG 16384
#define PROJ_SMEM (2 * PSTG * 2)

template <int MODE>
__device__ __forceinline__
void proj_body(const uint4* __restrict__ Ahi, const uint4* __restrict__ Alo,
               const uint4* __restrict__ Bhi, const uint4* __restrict__ Blo,
               const float* __restrict__ bias, void* __restrict__ outp,
               ushort* ps)
{
    const uint32_t sbase = smem_u32(ps);

    const int tid = threadIdx.x;
    const int lane = tid & 31, wid = tid >> 5;
    const int g = lane >> 2, t = lane & 3;
    const int m0 = blockIdx.y * 128;
    const int n0 = blockIdx.x * 128;
    const int wm = (wid & 3) * 32;
    const int wn = (wid >> 2) * 64;

    float d[2][8][4];
#pragma unroll
    for (int mt = 0; mt < 2; mt++)
#pragma unroll
        for (int nt = 0; nt < 8; nt++)
#pragma unroll
            for (int e = 0; e < 4; e++) d[mt][nt][e] = 0.f;

    auto load_stage = [&](int stage, int it) {
        const int k0 = it * 32;
        const uint32_t sb = sbase + stage * (PSTG * 2);
#pragma unroll
        for (int s = 0; s < 2; s++) {
            int idx = tid + s * 256;
            int r = idx >> 2, gg = idx & 3;
            uint32_t doff = (uint32_t)(r * 32 + ((gg ^ ((r >> 1) & 3)) * 8)) * 2;
            size_t ia;
            if (MODE == 0) {
                ia = (size_t)(m0 + r) * 128 + (k0 >> 3) + gg;
            } else {
                int m = m0 + r;
                int b = m >> 11, ss2 = m & (SS - 1);
                int h = k0 >> 6;
                ia = ((size_t)((b * NH + h) * SS + ss2)) * 8 + ((k0 & 63) >> 3) + gg;
            }
            size_t ib = (size_t)(n0 + r) * 128 + (k0 >> 3) + gg;
            cpa16(sb + doff,         &Ahi[ia]);
            cpa16(sb + 8192 + doff,  &Alo[ia]);
            cpa16(sb + 16384 + doff, &Bhi[ib]);
            cpa16(sb + 24576 + doff, &Blo[ib]);
        }
    };

    load_stage(0, 0);
    CP_COMMIT();

    for (int it = 0; it < 32; ++it) {
        const int cur = it & 1;
        if (it < 31) { load_stage(cur ^ 1, it + 1); CP_COMMIT(); }
        if (it < 31) { CP_WAIT(1); } else { CP_WAIT(0); }
        __syncthreads();

        const uint32_t sb = sbase + cur * (PSTG * 2);
#pragma unroll
        for (int ks = 0; ks < 2; ks++) {
            // shared fragment addresses for this ks
            uint32_t aoff[2], boff[4];
#pragma unroll
            for (int mt = 0; mt < 2; mt++) {
                int row = wm + 16 * mt + (lane & 15);
                int gg = (2 * ks + (lane >> 4)) ^ ((row >> 1) & 3);
                aoff[mt] = (uint32_t)(row * 32 + gg * 8) * 2;
            }
#pragma unroll
            for (int p = 0; p < 4; p++) {
                int row = wn + 16 * p + ((lane >> 4) << 3) + (lane & 7);
                int gg = (2 * ks + ((lane >> 3) & 1)) ^ ((row >> 1) & 3);
                boff[p] = (uint32_t)(row * 32 + gg * 8) * 2;
            }

            {   // pass 1: A-hi x (B-hi + B-lo)
                uint32_t af[2][4];
                ldmx4(af[0], sb + aoff[0]);
                ldmx4(af[1], sb + aoff[1]);
#pragma unroll
                for (int p = 0; p < 4; p++) {
                    uint32_t bf[4];
                    ldmx4(bf, sb + 16384 + boff[p]);
#pragma unroll
                    for (int mt = 0; mt < 2; mt++) {
                        mma_bf16(d[mt][2 * p],     af[mt][0], af[mt][1], af[mt][2], af[mt][3], bf[0], bf[1]);
                        mma_bf16(d[mt][2 * p + 1], af[mt][0], af[mt][1], af[mt][2], af[mt][3], bf[2], bf[3]);
                    }
                    ldmx4(bf, sb + 24576 + boff[p]);
#pragma unroll
                    for (int mt = 0; mt < 2; mt++) {
                        mma_bf16(d[mt][2 * p],     af[mt][0], af[mt][1], af[mt][2], af[mt][3], bf[0], bf[1]);
                        mma_bf16(d[mt][2 * p + 1], af[mt][0], af[mt][1], af[mt][2], af[mt][3], bf[2], bf[3]);
                    }
                }
            }
            {   // pass 2: A-lo x B-hi
                uint32_t af[2][4];
                ldmx4(af[0], sb + 8192 + aoff[0]);
                ldmx4(af[1], sb + 8192 + aoff[1]);
#pragma unroll
                for (int p = 0; p < 4; p++) {
                    uint32_t bf[4];
                    ldmx4(bf, sb + 16384 + boff[p]);
#pragma unroll
                    for (int mt = 0; mt < 2; mt++) {
                        mma_bf16(d[mt][2 * p],     af[mt][0], af[mt][1], af[mt][2], af[mt][3], bf[0], bf[1]);
                        mma_bf16(d[mt][2 * p + 1], af[mt][0], af[mt][1], af[mt][2], af[mt][3], bf[2], bf[3]);
                    }
                }
            }
        }
        __syncthreads();
    }

    // epilogue
#pragma unroll
    for (int mt = 0; mt < 2; mt++) {
#pragma unroll
        for (int nt = 0; nt < 8; nt++) {
            int m = m0 + wm + 16 * mt + g;
            int n = n0 + wn + 8 * nt + 2 * t;
            float2 bv = *(const float2*)&bias[n];
            float v0 = d[mt][nt][0] + bv.x, v1 = d[mt][nt][1] + bv.y;
            float v2 = d[mt][nt][2] + bv.x, v3 = d[mt][nt][3] + bv.y;
            if (MODE == 0) {
                int h = n >> 6, dh = n & 63;
                int b = m >> 11, ss2 = m & (SS - 1);
                __half* o = (__half*)outp;
                size_t o0 = ((size_t)((b * NH + h) * SS + ss2)) * DH + dh;
                size_t o1 = ((size_t)((b * NH + h) * SS + ss2 + 8)) * DH + dh;
                *(__half2*)&o[o0] = __floats2half2_rn(v0, v1);
                *(__half2*)&o[o1] = __floats2half2_rn(v2, v3);
            } else {
                float* o = (float*)outp;
                *(float2*)&o[(size_t)m * DM + n] = make_float2(v0, v1);
                *(float2*)&o[(size_t)(m + 8) * DM + n] = make_float2(v2, v3);
            }
        }
    }
}

// Merged Q/K/V projection: blockIdx.z selects the GEMM. 2 CTAs/SM.
__global__ __launch_bounds__(256, 2)
void proj_qkv(const uint4* Ah0, const uint4* Al0, const uint4* Bh0, const uint4* Bl0,
              const float* b0, void* o0,
              const uint4* Ah1, const uint4* Al1, const uint4* Bh1, const uint4* Bl1,
              const float* b1, void* o1,
              const uint4* Ah2, const uint4* Al2, const uint4* Bh2, const uint4* Bl2,
              const float* b2, void* o2)
{
    extern __shared__ __align__(16) ushort ps[];
    int z = blockIdx.z;
    const uint4* Ahi = (z == 0) ? Ah0 : (z == 1) ? Ah1 : Ah2;
    const uint4* Alo = (z == 0) ? Al0 : (z == 1) ? Al1 : Al2;
    const uint4* Bhi = (z == 0) ? Bh0 : (z == 1) ? Bh1 : Bh2;
    const uint4* Blo = (z == 0) ? Bl0 : (z == 1) ? Bl1 : Bl2;
    const float* bias = (z == 0) ? b0 : (z == 1) ? b1 : b2;
    void* outp = (z == 0) ? o0 : (z == 1) ? o1 : o2;
    proj_body<0>(Ahi, Alo, Bhi, Blo, bias, outp, ps);
}

// Output projection (A gathered from head-split attention output).
__global__ __launch_bounds__(256, 2)
void proj_o(const uint4* __restrict__ Ahi, const uint4* __restrict__ Alo,
            const uint4* __restrict__ Bhi, const uint4* __restrict__ Blo,
            const float* __restrict__ bias, void* __restrict__ outp)
{
    extern __shared__ __align__(16) ushort ps[];
    proj_body<1>(Ahi, Alo, Bhi, Blo, bias, outp, ps);
}

// ---------------- flash attention (round-11 proven: q-tile 128) -------------
__global__ __launch_bounds__(128)
void flash_attn()
{
    __shared__ __align__(16) ushort Qs[128 * 64];
    __shared__ __align__(16) ushort Ks[2][64 * 64];
    __shared__ __align__(16) ushort Vs[2][64 * 64];

    const int tid = threadIdx.x;
    const int lane = tid & 31, w = tid >> 5;
    const int g = lane >> 2, t = lane & 3;
    const int bh = blockIdx.y, b = bh >> 4;
    const int q0 = blockIdx.x * 128;

    const float C1 = 0.125f * 1.4426950408889634f;
    const float SC = 0.015625f;

    const uint32_t Qb  = smem_u32(Qs);
    const uint32_t Kb0 = smem_u32(Ks);
    const uint32_t Vb0 = smem_u32(Vs);

    const uint4* qsrc = (const uint4*)g_qh;
#pragma unroll
    for (int s = 0; s < 8; s++) {
        int f = tid + s * 128;
        int r = f >> 3, c = f & 7;
        uint4 v = qsrc[((size_t)bh * SS + q0 + r) * 8 + c];
        *(uint4*)&Qs[r * 64 + ((c ^ (r & 7)) << 3)] = v;
    }

    const char* ksrc = (const char*)(g_kh + (size_t)bh * SS * DH);
    const char* vsrc = (const char*)(g_vh + (size_t)bh * SS * DH);

    auto load_kv = [&](int stage, int kt) {
#pragma unroll
        for (int s = 0; s < 4; s++) {
            int f = tid + s * 128;
            int r = f >> 3, c = f & 7;
            uint32_t doff = (uint32_t)(r * 64 + ((c ^ (r & 7)) << 3)) * 2;
            size_t go = ((size_t)(kt + r) * 8 + c) * 16;
            cpa16(Kb0 + stage * 8192 + doff, ksrc + go);
            cpa16(Vb0 + stage * 8192 + doff, vsrc + go);
        }
    };

    float O[2][8][4];
#pragma unroll
    for (int mt = 0; mt < 2; mt++)
#pragma unroll
        for (int j = 0; j < 8; j++)
#pragma unroll
            for (int e = 0; e < 4; e++) O[mt][j][e] = 0.f;
    float lsum[2][2] = {{0.f, 0.f}, {0.f, 0.f}};

    load_kv(0, 0);
    CP_COMMIT();

    for (int itn = 0; itn < 32; ++itn) {
        const int cur = itn & 1;
        const int kt = itn * 64;
        if (itn < 31) { load_kv(cur ^ 1, kt + 64); CP_COMMIT(); }
        if (itn < 31) { CP_WAIT(1); } else { CP_WAIT(0); }
        __syncthreads();

        const uint32_t Kb = Kb0 + cur * 8192;
        const uint32_t Vb = Vb0 + cur * 8192;

        uint32_t pA[2][8], pB[2][8];

#pragma unroll
        for (int mt = 0; mt < 2; mt++) {
            float sd[8][4];
#pragma unroll
            for (int j = 0; j < 8; j++)
#pragma unroll
                for (int e = 0; e < 4; e++) sd[j][e] = 0.f;

#pragma unroll
            for (int ks = 0; ks < 4; ks++) {
                uint32_t a4[4];
                {
                    int row = 32 * w + 16 * mt + (lane & 15);
                    int gg = (2 * ks + (lane >> 4)) ^ (row & 7);
                    ldmx4(a4, Qb + (uint32_t)(row * 64 + gg * 8) * 2);
                }
#pragma unroll
                for (int p = 0; p < 4; p++) {
                    int row = 16 * p + ((lane >> 4) << 3) + (lane & 7);
                    int gg = (2 * ks + ((lane >> 3) & 1)) ^ (row & 7);
                    uint32_t b4[4];
                    ldmx4(b4, Kb + (uint32_t)(row * 64 + gg * 8) * 2);
                    mma_f16(sd[2 * p],     a4[0], a4[1], a4[2], a4[3], b4[0], b4[1]);
                    mma_f16(sd[2 * p + 1], a4[0], a4[1], a4[2], a4[3], b4[2], b4[3]);
                }
            }

            const __half2* mrow0 =
                (const __half2*)&g_mh[((size_t)b * SS + q0 + 32 * w + 16 * mt + g) * SS + kt];
            const __half2* mrow1 =
                (const __half2*)&g_mh[((size_t)b * SS + q0 + 32 * w + 16 * mt + g + 8) * SS + kt];
#pragma unroll
            for (int j = 0; j < 8; j++) {
                float2 mb0 = __half22float2(mrow0[4 * j + t]);
                float2 mb1 = __half22float2(mrow1[4 * j + t]);
                float p0 = ex2(fmaf(sd[j][0], C1, mb0.x));
                float p1 = ex2(fmaf(sd[j][1], C1, mb0.y));
                float p2 = ex2(fmaf(sd[j][2], C1, mb1.x));
                float p3 = ex2(fmaf(sd[j][3], C1, mb1.y));
                lsum[mt][0] += p0 + p1;
                lsum[mt][1] += p2 + p3;
                pA[mt][j] = pack2h(p0 * SC, p1 * SC);
                pB[mt][j] = pack2h(p2 * SC, p3 * SC);
            }
        }

#pragma unroll
        for (int c2 = 0; c2 < 4; c2++) {
#pragma unroll
            for (int jp = 0; jp < 4; jp++) {
                int row = 16 * c2 + (((lane >> 3) & 1) << 3) + (lane & 7);
                int gg = (2 * jp + (lane >> 4)) ^ (row & 7);
                uint32_t b4[4];
                ldmx4t(b4, Vb + (uint32_t)(row * 64 + gg * 8) * 2);
#pragma unroll
                for (int mt = 0; mt < 2; mt++) {
                    mma_f16(O[mt][2 * jp],     pA[mt][2 * c2], pB[mt][2 * c2],
                            pA[mt][2 * c2 + 1], pB[mt][2 * c2 + 1], b4[0], b4[1]);
                    mma_f16(O[mt][2 * jp + 1], pA[mt][2 * c2], pB[mt][2 * c2],
                            pA[mt][2 * c2 + 1], pB[mt][2 * c2 + 1], b4[2], b4[3]);
                }
            }
        }
        __syncthreads();
    }

#pragma unroll
    for (int mt = 0; mt < 2; mt++) {
        float l0 = lsum[mt][0], l1 = lsum[mt][1];
        l0 += __shfl_xor_sync(0xffffffffu, l0, 1);
        l0 += __shfl_xor_sync(0xffffffffu, l0, 2);
        l1 += __shfl_xor_sync(0xffffffffu, l1, 1);
        l1 += __shfl_xor_sync(0xffffffffu, l1, 2);
        const float inv0 = 64.f / l0;
        const float inv1 = 64.f / l1;

        size_t off0 = ((size_t)bh * SS + q0 + 32 * w + 16 * mt + g) * DH;
        size_t off1 = ((size_t)bh * SS + q0 + 32 * w + 16 * mt + g + 8) * DH;
#pragma unroll
        for (int j = 0; j < 8; j++) {
            int dh = 8 * j + 2 * t;
            float v0 = O[mt][j][0] * inv0, v1 = O[mt][j][1] * inv0;
            float v2 = O[mt][j][2] * inv1, v3 = O[mt][j][3] * inv1;
            __nv_bfloat16 h0 = __float2bfloat16(v0), h1 = __float2bfloat16(v1);
            __nv_bfloat16 h2 = __float2bfloat16(v2), h3 = __float2bfloat16(v3);
            __nv_bfloat16 e0 = __float2bfloat16(v0 - __bfloat162float(h0));
            __nv_bfloat16 e1 = __float2bfloat16(v1 - __bfloat162float(h1));
            __nv_bfloat16 e2 = __float2bfloat16(v2 - __bfloat162float(h2));
            __nv_bfloat16 e3 = __float2bfloat16(v3 - __bfloat162float(h3));
            *(__nv_bfloat162*)&g_att_hi[off0 + dh] = __nv_bfloat162(h0, h1);
            *(__nv_bfloat162*)&g_att_lo[off0 + dh] = __nv_bfloat162(e0, e1);
            *(__nv_bfloat162*)&g_att_hi[off1 + dh] = __nv_bfloat162(h2, h3);
            *(__nv_bfloat162*)&g_att_lo[off1 + dh] = __nv_bfloat162(e2, e3);
        }
    }
}

// ---------------------------------------------------------------------------
extern "C" void kernel_launch(void* const* d_in, const int* in_sizes, int n_in,
                              void* d_out, int out_size)
{
    const float* q    = (const float*)d_in[0];
    const float* k    = (const float*)d_in[1];
    const float* v    = (const float*)d_in[2];
    const float* mask = (const float*)d_in[3];
    const float* wq   = (const float*)d_in[4];
    const float* bq   = (const float*)d_in[5];
    const float* wk   = (const float*)d_in[6];
    const float* bk   = (const float*)d_in[7];
    const float* wv   = (const float*)d_in[8];
    const float* bv   = (const float*)d_in[9];
    const float* wo   = (const float*)d_in[10];
    const float* bo   = (const float*)d_in[11];
    float* out = (float*)d_out;

    void *qh_, *ql_, *kh_, *kl_, *vh_, *vl_;
    void *wqh_, *wql_, *wkh_, *wkl_, *wvh_, *wvl_, *woh_, *wol_;
    void *pqh_, *pkh_, *pvh_, *ath_, *atl_, *mh_;
    cudaGetSymbolAddress(&qh_, g_q_hi);   cudaGetSymbolAddress(&ql_, g_q_lo);
    cudaGetSymbolAddress(&kh_, g_k_hi);   cudaGetSymbolAddress(&kl_, g_k_lo);
    cudaGetSymbolAddress(&vh_, g_v_hi);   cudaGetSymbolAddress(&vl_, g_v_lo);
    cudaGetSymbolAddress(&wqh_, g_wq_hi); cudaGetSymbolAddress(&wql_, g_wq_lo);
    cudaGetSymbolAddress(&wkh_, g_wk_hi); cudaGetSymbolAddress(&wkl_, g_wk_lo);
    cudaGetSymbolAddress(&wvh_, g_wv_hi); cudaGetSymbolAddress(&wvl_, g_wv_lo);
    cudaGetSymbolAddress(&woh_, g_wo_hi); cudaGetSymbolAddress(&wol_, g_wo_lo);
    cudaGetSymbolAddress(&pqh_, g_qh);    cudaGetSymbolAddress(&pkh_, g_kh);
    cudaGetSymbolAddress(&pvh_, g_vh);
    cudaGetSymbolAddress(&ath_, g_att_hi); cudaGetSymbolAddress(&atl_, g_att_lo);
    cudaGetSymbolAddress(&mh_, g_mh);

    cudaFuncSetAttribute(proj_qkv, cudaFuncAttributeMaxDynamicSharedMemorySize, PROJ_SMEM);
    cudaFuncSetAttribute(proj_o,   cudaFuncAttributeMaxDynamicSharedMemorySize, PROJ_SMEM);

    // Launch 1: q,k,v splits (grid.z = 3)
    {
        dim3 sgrid(MM * DM / 4 / 256, 1, 3);
        split_qkv<<<sgrid, 256>>>(
            (const float4*)q, (const float4*)k, (const float4*)v,
            (__nv_bfloat162*)qh_, (__nv_bfloat162*)kh_, (__nv_bfloat162*)vh_,
            (__nv_bfloat162*)ql_, (__nv_bfloat162*)kl_, (__nv_bfloat162*)vl_);
    }
    // Launch 2: weight splits (grid.z = 4)
    {
        dim3 sgrid(DM * DM / 4 / 256, 1, 4);
        split_w<<<sgrid, 256>>>(
            (const float4*)wq, (const float4*)wk, (const float4*)wv, (const float4*)wo,
            (__nv_bfloat162*)wqh_, (__nv_bfloat162*)wkh_, (__nv_bfloat162*)wvh_,
            (__nv_bfloat162*)woh_,
            (__nv_bfloat162*)wql_, (__nv_bfloat162*)wkl_, (__nv_bfloat162*)wvl_,
            (__nv_bfloat162*)wol_);
    }
    // Launch 3: mask -> fp16 bias
    pre_mask<<<BB * SS * SS / 4 / 256, 256>>>((const float4*)mask, (__half2*)mh_);

    // Launch 4: merged Q/K/V projections (grid.z = 3)
    {
        dim3 pgrid(DM / 128, MM / 128, 3);   // (8, 32, 3)
        proj_qkv<<<pgrid, 256, PROJ_SMEM>>>(
            (const uint4*)qh_, (const uint4*)ql_, (const uint4*)wqh_, (const uint4*)wql_, bq, pqh_,
            (const uint4*)kh_, (const uint4*)kl_, (const uint4*)wkh_, (const uint4*)wkl_, bk, pkh_,
            (const uint4*)vh_, (const uint4*)vl_, (const uint4*)wvh_, (const uint4*)wvl_, bv, pvh_);
    }

    // Launch 5: attention
    dim3 agrid(SS / 128, BB * NH);    // (16, 32)
    flash_attn<<<agrid, 128>>>();

    // Launch 6 (ncu target): output projection
    dim3 ogrid(DM / 128, MM / 128);   // (8, 32)
    proj_o<<<ogrid, 256, PROJ_SMEM>>>((const uint4*)ath_, (const uint4*)atl_,
                                      (const uint4*)woh_, (const uint4*)wol_, bo, out);
}